// round 16
// baseline (speedup 1.0000x reference)
#include <cuda_runtime.h>
#include <cuda_bf16.h>
#include <cstdint>

#define NN 50000
#define NE 800000

// Scratch: __device__ globals (no allocation allowed).
// g_y[n*32+u] = {ys, yv0..2} post-lin1.
// g_mid[n*64 + 2u] = A_u {o_s_a, o_v_a}, g_mid[n*64 + 2u+1] = B_u {o_s_b, o_v_b}.
// Interleaved so one edge's whole contribution is a contiguous 1KB block
// (target of one cp.reduce.async.bulk).
__device__ float4 g_y[NN * 32];
__device__ float4 g_mid[NN * 64];

// ---------------------------------------------------------------------------
// Kernel 1: per-node prep + zero mid accumulators. TWO nodes per warp
// (weight-LDS amortized).
// ---------------------------------------------------------------------------
__global__ void node_prep_kernel(const float* __restrict__ nf,
                                 const float* __restrict__ nattr,
                                 const float* __restrict__ W1s,
                                 const float* __restrict__ W1v,
                                 const float* __restrict__ Wscs,
                                 const float* __restrict__ Wscv,
                                 float* __restrict__ out) {
    __shared__ float2 sW1[1024];      // [u][w] -> {W1s, W1v}            8KB
    __shared__ float2 sWsc[4096];     // [u][sp][w] -> {Wscs, Wscv}     32KB
    __shared__ float4 sBuf[8][2][32]; // per-warp, 2 nodes, repacked row  8KB

    const int tid = threadIdx.x;
    for (int i = tid; i < 1024; i += 256) sW1[i] = make_float2(W1s[i], W1v[i]);
    for (int i = tid; i < 4096; i += 256) sWsc[i] = make_float2(Wscs[i], Wscv[i]);
    __syncthreads();

    const int warp = tid >> 5, lane = tid & 31;
    const int nwarps = gridDim.x * 8;
    const float l1n = 0.17677669529663687f;  // 1/sqrt(32)
    const float scn = 0.08838834764831843f;  // 1/sqrt(32*4)
    const float4 z4 = make_float4(0.f, 0.f, 0.f, 0.f);

    for (int n0 = (blockIdx.x * 8 + warp) * 2; n0 < NN; n0 += nwarps * 2) {
        const int n1 = n0 + 1;   // NN even

        sBuf[warp][0][lane] = __ldg((const float4*)(nf + (size_t)n0 * 128) + lane);
        sBuf[warp][1][lane] = __ldg((const float4*)(nf + (size_t)n1 * 128) + lane);
        g_mid[n0 * 64 + lane]      = z4;
        g_mid[n0 * 64 + 32 + lane] = z4;
        g_mid[n1 * 64 + lane]      = z4;
        g_mid[n1 * 64 + 32 + lane] = z4;
        __syncwarp();

        const float* r0 = (const float*)sBuf[warp][0];
        const float* r1 = (const float*)sBuf[warp][1];
        float a_s = r0[lane], a0 = r0[32 + lane * 3 + 0],
              a1 = r0[32 + lane * 3 + 1], a2 = r0[32 + lane * 3 + 2];
        float b_s = r1[lane], b0 = r1[32 + lane * 3 + 0],
              b1 = r1[32 + lane * 3 + 1], b2 = r1[32 + lane * 3 + 2];
        __syncwarp();
        sBuf[warp][0][lane] = make_float4(a_s, a0, a1, a2);
        sBuf[warp][1][lane] = make_float4(b_s, b0, b1, b2);
        __syncwarp();

        int sp0 = 0, sp1 = 0;
#pragma unroll
        for (int v = 0; v < 4; v++) {
            if (nattr[n0 * 4 + v] > 0.5f) sp0 = v;
            if (nattr[n1 * 4 + v] > 0.5f) sp1 = v;
        }

        const int w = lane;
        float ysA = 0.f, y0A = 0.f, y1A = 0.f, y2A = 0.f;
        float ssA = 0.f, s0A = 0.f, s1A = 0.f, s2A = 0.f;
        float ysB = 0.f, y0B = 0.f, y1B = 0.f, y2B = 0.f;
        float ssB = 0.f, s0B = 0.f, s1B = 0.f, s2B = 0.f;
        const float2* wscA = sWsc + sp0 * 32 + w;
        const float2* wscB = sWsc + sp1 * 32 + w;
#pragma unroll 8
        for (int u = 0; u < 32; u++) {
            float4 xa = sBuf[warp][0][u];
            float4 xb = sBuf[warp][1][u];
            float2 ab = sW1[u * 32 + w];
            ysA = fmaf(xa.x, ab.x, ysA);  ysB = fmaf(xb.x, ab.x, ysB);
            y0A = fmaf(xa.y, ab.y, y0A);  y0B = fmaf(xb.y, ab.y, y0B);
            y1A = fmaf(xa.z, ab.y, y1A);  y1B = fmaf(xb.z, ab.y, y1B);
            y2A = fmaf(xa.w, ab.y, y2A);  y2B = fmaf(xb.w, ab.y, y2B);
            float2 ca = wscA[u * 128];
            float2 cb = wscB[u * 128];
            ssA = fmaf(xa.x, ca.x, ssA);  ssB = fmaf(xb.x, cb.x, ssB);
            s0A = fmaf(xa.y, ca.y, s0A);  s0B = fmaf(xb.y, cb.y, s0B);
            s1A = fmaf(xa.z, ca.y, s1A);  s1B = fmaf(xb.z, cb.y, s1B);
            s2A = fmaf(xa.w, ca.y, s2A);  s2B = fmaf(xb.w, cb.y, s2B);
        }

        g_y[n0 * 32 + w] = make_float4(ysA * l1n, y0A * l1n, y1A * l1n, y2A * l1n);
        g_y[n1 * 32 + w] = make_float4(ysB * l1n, y0B * l1n, y1B * l1n, y2B * l1n);

        float* o0 = out + (size_t)n0 * 128;
        o0[w] = ssA * scn;
        o0[32 + w * 3 + 0] = s0A * scn;
        o0[32 + w * 3 + 1] = s1A * scn;
        o0[32 + w * 3 + 2] = s2A * scn;
        float* o1 = out + (size_t)n1 * 128;
        o1[w] = ssB * scn;
        o1[32 + w * 3 + 0] = s0B * scn;
        o1[32 + w * 3 + 1] = s1B * scn;
        o1[32 + w * 3 + 2] = s2B * scn;
        __syncwarp();
    }
}

// ---------------------------------------------------------------------------
// Kernel 2: edge kernel. Warp per EDGE PAIR, lane = channel u.
// Scatter-add via TMA bulk reduction (cp.reduce.async.bulk), now TRIPLE
// buffered (depth-3 pipeline, wait_group.read 2) to hide bulk-reduce latency.
// Cooperative silu covers both edges in one MUFU pass (lanes 0-15).
// ---------------------------------------------------------------------------
__global__ void __launch_bounds__(256) edge_kernel(
                            const float* __restrict__ eb,
                            const float* __restrict__ ea,
                            const int* __restrict__ ei,
                            const float* __restrict__ fw1,
                            const float* __restrict__ fw2) {
    // [warp][depth 3][edge-in-pair][64 float4] = 48KB exactly
    __shared__ float4 sbuf[8][3][2][64];

    const int tid = threadIdx.x;
    const int warp = tid >> 5, lane = tid & 31;
    const int nwarps = gridDim.x * 8;
    const float is8 = 0.3535533905932738f;  // 1/sqrt(8)
    const float IS3 = 0.5773502691896258f;  // 1/sqrt(3)
    const int u = lane;

    float w1r[8];
#pragma unroll
    for (int k = 0; k < 8; k++) w1r[k] = __ldg(fw1 + k * 8 + (lane & 7));
    float w2r[32];
#pragma unroll
    for (int j = 0; j < 8; j++)
#pragma unroll
        for (int c = 0; c < 4; c++)
            w2r[j * 4 + c] = __ldg(fw2 + j * 128 + c * 32 + u);

    int p = 0;
    const int ntasks = NE / 2;
    for (int t = blockIdx.x * 8 + warp; t < ntasks; t += nwarps) {
        const int e0 = 2 * t;
        const int2 src01 = __ldg((const int2*)(ei + e0));
        const int2 dst01 = __ldg((const int2*)(ei + NE + e0));

        const float4 ya  = __ldg(&g_y[src01.x * 32 + u]);
        const float4 yb  = __ldg(&g_y[src01.y * 32 + u]);
        const float4 av0 = __ldg((const float4*)(ea + (size_t)e0 * 4));
        const float4 av1 = __ldg((const float4*)(ea + (size_t)e0 * 4 + 4));

        // cooperative MLP layer 1 for BOTH edges: lanes 0-7 -> edge0,
        // lanes 8-15 -> edge1; one silu MUFU pass covers both.
        float ebv = (lane < 16)
            ? __ldg(eb + (size_t)(e0 + (lane >> 3)) * 8 + (lane & 7)) : 0.f;
        float acc = 0.f;
        const int gbase = lane & 8;   // 0 for edge0 lanes, 8 for edge1 lanes
#pragma unroll
        for (int k = 0; k < 8; k++)
            acc = fmaf(__shfl_sync(0xffffffffu, ebv, gbase + k), w1r[k], acc);
        acc *= is8;
        float hv = __fdividef(acc, 1.f + __expf(-acc));   // silu

        // layer 2 for both edges (register weights)
        float w00a = 0.f, w01a = 0.f, w10a = 0.f, w11a = 0.f;
        float w00b = 0.f, w01b = 0.f, w10b = 0.f, w11b = 0.f;
#pragma unroll
        for (int j = 0; j < 8; j++) {
            const float hj0 = __shfl_sync(0xffffffffu, hv, j);
            const float hj1 = __shfl_sync(0xffffffffu, hv, 8 + j);
            w00a = fmaf(hj0, w2r[j * 4 + 0], w00a);
            w01a = fmaf(hj0, w2r[j * 4 + 1], w01a);
            w10a = fmaf(hj0, w2r[j * 4 + 2], w10a);
            w11a = fmaf(hj0, w2r[j * 4 + 3], w11a);
            w00b = fmaf(hj1, w2r[j * 4 + 0], w00b);
            w01b = fmaf(hj1, w2r[j * 4 + 1], w01b);
            w10b = fmaf(hj1, w2r[j * 4 + 2], w10b);
            w11b = fmaf(hj1, w2r[j * 4 + 3], w11b);
        }

        // edge 0 outputs
        const float esa    = ya.x;
        const float dotva  = fmaf(ya.y, av0.y, fmaf(ya.z, av0.z, ya.w * av0.w));
        const float wesa   = w01a * is8 * esa;
        const float w10a0a = w10a * is8 * av0.x;
        float4 A0 = make_float4(w00a * is8 * esa * av0.x,
                                wesa * av0.y, wesa * av0.z, wesa * av0.w);
        float4 B0 = make_float4(w11a * is8 * dotva * IS3,
                                w10a0a * ya.y, w10a0a * ya.z, w10a0a * ya.w);
        // edge 1 outputs
        const float esb    = yb.x;
        const float dotvb  = fmaf(yb.y, av1.y, fmaf(yb.z, av1.z, yb.w * av1.w));
        const float wesb   = w01b * is8 * esb;
        const float w10a0b = w10b * is8 * av1.x;
        float4 A1 = make_float4(w00b * is8 * esb * av1.x,
                                wesb * av1.y, wesb * av1.z, wesb * av1.w);
        float4 B1 = make_float4(w11b * is8 * dotvb * IS3,
                                w10a0b * yb.y, w10a0b * yb.z, w10a0b * yb.w);

        // allow up to 2 outstanding bulk groups; buffer p is then free
        if (lane == 0)
            asm volatile("cp.async.bulk.wait_group.read 2;" ::: "memory");
        __syncwarp();

        sbuf[warp][p][0][lane * 2]     = A0;
        sbuf[warp][p][0][lane * 2 + 1] = B0;
        sbuf[warp][p][1][lane * 2]     = A1;
        sbuf[warp][p][1][lane * 2 + 1] = B1;
        __syncwarp();

        if (lane == 0) {
            asm volatile("fence.proxy.async.shared::cta;" ::: "memory");
            unsigned int s0 = (unsigned int)__cvta_generic_to_shared(&sbuf[warp][p][0][0]);
            unsigned int s1 = s0 + 1024u;
            asm volatile(
                "cp.reduce.async.bulk.global.shared::cta.bulk_group.add.f32 [%0], [%1], %2;"
                :: "l"(g_mid + (size_t)dst01.x * 64), "r"(s0), "r"(1024)
                : "memory");
            asm volatile(
                "cp.reduce.async.bulk.global.shared::cta.bulk_group.add.f32 [%0], [%1], %2;"
                :: "l"(g_mid + (size_t)dst01.y * 64), "r"(s1), "r"(1024)
                : "memory");
            asm volatile("cp.async.bulk.commit_group;" ::: "memory");
        }
        p = (p == 2) ? 0 : p + 1;
    }
    // TMA writes are flushed before kernel completion; nothing further needed.
}

// ---------------------------------------------------------------------------
// Kernel 3: per-node output, TWO nodes per warp. Reads interleaved g_mid;
// lin2 weights pre-permuted into smem so the inner loop stays identical.
// ---------------------------------------------------------------------------
__global__ void node_out_kernel(const float* __restrict__ W2s,
                                const float* __restrict__ W2v,
                                float* __restrict__ out) {
    __shared__ float2 sW2[2048];      // permuted [uu][w]             16KB
    __shared__ float4 sMid[8][128];   // 2 nodes x 64 per warp        16KB

    const int tid = threadIdx.x;
    for (int i = tid; i < 2048; i += 256) {
        int uu = i >> 5, w = i & 31;
        int row = (uu & 1) ? (32 + (uu >> 1)) : (uu >> 1);
        sW2[i] = make_float2(W2s[row * 32 + w], W2v[row * 32 + w]);
    }
    __syncthreads();

    const int warp = tid >> 5, lane = tid & 31;
    const int nwarps = gridDim.x * 8;
    const float c = 0.25f * 0.125f;  // 1/sqrt(16) * 1/sqrt(64)

    for (int n0 = (blockIdx.x * 8 + warp) * 2; n0 < NN; n0 += nwarps * 2) {
        const int n1 = n0 + 1;

        sMid[warp][lane]       = g_mid[n0 * 64 + lane];
        sMid[warp][32 + lane]  = g_mid[n0 * 64 + 32 + lane];
        sMid[warp][64 + lane]  = g_mid[n1 * 64 + lane];
        sMid[warp][96 + lane]  = g_mid[n1 * 64 + 32 + lane];
        __syncwarp();

        const int w = lane;
        float osA = 0.f, v0A = 0.f, v1A = 0.f, v2A = 0.f;
        float osB = 0.f, v0B = 0.f, v1B = 0.f, v2B = 0.f;
#pragma unroll 16
        for (int uu = 0; uu < 64; uu++) {
            float4 ma = sMid[warp][uu];
            float4 mb = sMid[warp][64 + uu];
            float2 ab = sW2[uu * 32 + w];
            osA = fmaf(ma.x, ab.x, osA);  osB = fmaf(mb.x, ab.x, osB);
            v0A = fmaf(ma.y, ab.y, v0A);  v0B = fmaf(mb.y, ab.y, v0B);
            v1A = fmaf(ma.z, ab.y, v1A);  v1B = fmaf(mb.z, ab.y, v1B);
            v2A = fmaf(ma.w, ab.y, v2A);  v2B = fmaf(mb.w, ab.y, v2B);
        }

        float* o0 = out + (size_t)n0 * 128;
        o0[w]              += osA * c;
        o0[32 + w * 3 + 0] += v0A * c;
        o0[32 + w * 3 + 1] += v1A * c;
        o0[32 + w * 3 + 2] += v2A * c;
        float* o1 = out + (size_t)n1 * 128;
        o1[w]              += osB * c;
        o1[32 + w * 3 + 0] += v0B * c;
        o1[32 + w * 3 + 1] += v1B * c;
        o1[32 + w * 3 + 2] += v2B * c;
        __syncwarp();
    }
}

// ---------------------------------------------------------------------------
extern "C" void kernel_launch(void* const* d_in, const int* in_sizes, int n_in,
                              void* d_out, int out_size) {
    const float* nf    = (const float*)d_in[0];
    const float* nattr = (const float*)d_in[1];
    const float* eb    = (const float*)d_in[2];
    const float* ea    = (const float*)d_in[3];
    const int*   ei    = (const int*)d_in[4];
    const float* W1s   = (const float*)d_in[5];
    const float* W1v   = (const float*)d_in[6];
    const float* fw1   = (const float*)d_in[7];
    const float* fw2   = (const float*)d_in[8];
    const float* W2s   = (const float*)d_in[9];
    const float* W2v   = (const float*)d_in[10];
    const float* Wscs  = (const float*)d_in[11];
    const float* Wscv  = (const float*)d_in[12];
    float* out = (float*)d_out;

    node_prep_kernel<<<1184, 256>>>(nf, nattr, W1s, W1v, Wscs, Wscv, out);
    edge_kernel<<<1184, 256>>>(eb, ea, ei, fw1, fw2);
    node_out_kernel<<<1184, 256>>>(W2s, W2v, out);
}